// round 6
// baseline (speedup 1.0000x reference)
#include <cuda_runtime.h>
#include <cuda_fp16.h>
#include <cstdint>

#define TOKENS 8192
#define DIN    4096
#define DOUT   16384

// Scratch (device globals are the sanctioned scratch mechanism)
__device__ __half  g_xn[(size_t)TOKENS * DIN];   // layernormed x, fp16 (64 MB)
__device__ int8_t  g_ws[(size_t)DOUT * DIN];     // sign(W) int8, unit-permuted (64 MB)

__device__ __forceinline__ uint32_t smem_u32(const void* p) {
    uint32_t a;
    asm("{ .reg .u64 t; cvta.to.shared.u64 t, %1; cvt.u32.u64 %0, t; }"
        : "=r"(a) : "l"(p));
    return a;
}

// ---------------------------------------------------------------------------
// Kernel 1: row layernorm (fp32 stats, ddof=1), write fp16 to g_xn
// ---------------------------------------------------------------------------
__global__ __launch_bounds__(256) void ln_kernel(const float* __restrict__ x) {
    int row = blockIdx.x;
    const float4* xr = (const float4*)(x + (size_t)row * DIN);
    float4 v[4];
    float s = 0.f, ss = 0.f;
#pragma unroll
    for (int i = 0; i < 4; i++) {
        v[i] = xr[threadIdx.x + i * 256];
        s  += v[i].x + v[i].y + v[i].z + v[i].w;
        ss += v[i].x * v[i].x + v[i].y * v[i].y + v[i].z * v[i].z + v[i].w * v[i].w;
    }
#pragma unroll
    for (int o = 16; o > 0; o >>= 1) {
        s  += __shfl_xor_sync(0xFFFFFFFFu, s, o);
        ss += __shfl_xor_sync(0xFFFFFFFFu, ss, o);
    }
    __shared__ float sh[2][8];
    __shared__ float sh_mean, sh_inv;
    int wid = threadIdx.x >> 5, lane = threadIdx.x & 31;
    if (lane == 0) { sh[0][wid] = s; sh[1][wid] = ss; }
    __syncthreads();
    if (threadIdx.x == 0) {
        float S = 0.f, SS = 0.f;
#pragma unroll
        for (int i = 0; i < 8; i++) { S += sh[0][i]; SS += sh[1][i]; }
        float mean = S * (1.f / DIN);
        float var  = fmaxf((SS - S * mean) * (1.f / (DIN - 1)), 0.f);
        sh_mean = mean;
        sh_inv  = 1.f / (sqrtf(var) + 1e-5f);
    }
    __syncthreads();
    float mean = sh_mean, inv = sh_inv;
    __half2* orow = (__half2*)(g_xn + (size_t)row * DIN);
#pragma unroll
    for (int i = 0; i < 4; i++) {
        int j = threadIdx.x + i * 256;
        orow[j * 2 + 0] = __floats2half2_rn((v[i].x - mean) * inv, (v[i].y - mean) * inv);
        orow[j * 2 + 1] = __floats2half2_rn((v[i].z - mean) * inv, (v[i].w - mean) * inv);
    }
}

// ---------------------------------------------------------------------------
// Kernel 2: binarize weights to int8 {-1,0,+1} with unit permutation inside
// each 16-byte group: logical b16-unit u (k-pair 2u,2u+1) stored at physical
// unit p = (u<4) ? 2u : 2(u-4)+1, so ldmatrix.b16 delivers units (q, q+4)
// per lane register (the m16n8k16 B fragment layout).
// ---------------------------------------------------------------------------
__global__ __launch_bounds__(256) void sign_kernel(const float* __restrict__ w) {
    size_t grp = (size_t)blockIdx.x * 256 + threadIdx.x;   // 16-element group
    const float4* src = (const float4*)(w + grp * 16);
    float4 f[4] = { src[0], src[1], src[2], src[3] };
    const float* fv = (const float*)f;
    unsigned char b[16];
#pragma unroll
    for (int k = 0; k < 16; k++) {
        float a = fv[k];
        signed char sg = (a > 0.f) ? 1 : ((a < 0.f) ? -1 : 0);
        int pos = (k < 8) ? (4 * (k >> 1) + (k & 1))
                          : (4 * ((k >> 1) - 4) + 2 + (k & 1));
        b[pos] = (unsigned char)sg;
    }
    *(uint4*)(g_ws + grp * 16) = *(const uint4*)b;
}

// ---------------------------------------------------------------------------
// Kernel 3: HMMA GEMM, CTA 128x128x64, 3-stage cp.async, 8 warps (2Mx4N),
//   warp tile 64x32. A in fp16 smem (128B rows, XOR swizzle);
//   B in int8 smem (80B padded rows, conflict-free), expanded to fp16 in regs.
// ---------------------------------------------------------------------------
constexpr int BM = 128, BN = 128, BK = 64;
constexpr int NK = DIN / BK;                 // 64 K-chunks
constexpr int ASZ = BM * 128;                // 16384 B (fp16 A tile)
constexpr int BROW = 80;                     // padded int8 B row (64 data + 16 pad)
constexpr int BSZ = BN * BROW;               // 10240 B
constexpr int STG = ASZ + BSZ;               // 26624 B per stage
constexpr int NSTAGE = 3;
constexpr int SMEM_TOTAL = NSTAGE * STG;     // 79872 B (x2 CTAs = 156 KB/SM)

__device__ __forceinline__ void ldmx4(uint32_t* r, uint32_t addr) {
    asm volatile("ldmatrix.sync.aligned.m8n8.x4.shared.b16 {%0,%1,%2,%3}, [%4];"
                 : "=r"(r[0]), "=r"(r[1]), "=r"(r[2]), "=r"(r[3]) : "r"(addr));
}

__device__ __forceinline__ void mma16816(float* c, const uint32_t* a, const uint32_t* b) {
    asm volatile(
        "mma.sync.aligned.m16n8k16.row.col.f32.f16.f16.f32 "
        "{%0,%1,%2,%3}, {%4,%5,%6,%7}, {%8,%9}, {%0,%1,%2,%3};"
        : "+f"(c[0]), "+f"(c[1]), "+f"(c[2]), "+f"(c[3])
        : "r"(a[0]), "r"(a[1]), "r"(a[2]), "r"(a[3]), "r"(b[0]), "r"(b[1]));
}

// expand sign-extended s16x2 {0,±1} -> fp16x2 {0,±1}
__device__ __forceinline__ uint32_t sext_to_half2(uint32_t s) {
    uint32_t mag = (s & 0x00010001u) * 0x3C00u;
    return mag | (s & 0x80008000u);
}

// load one stage: A fp16 (8x16B chunks/row) + B int8 (4x16B chunks/row)
__device__ __forceinline__ void load_stage(uint32_t sb, int buf, int kc,
                                           const __half* Ag, const int8_t* Bg, int tid) {
    uint32_t base = sb + buf * STG;
    int k0 = kc * BK;
#pragma unroll
    for (int i = 0; i < 4; i++) {               // A: 128 rows x 8 chunks
        int g = tid + i * 256;
        int row = g >> 3, c = g & 7;
        const void* src = Ag + (size_t)row * DIN + k0 + c * 8;
        uint32_t dst = base + row * 128 + ((c ^ (row & 7)) << 4);
        asm volatile("cp.async.cg.shared.global [%0], [%1], 16;" :: "r"(dst), "l"(src) : "memory");
    }
#pragma unroll
    for (int i = 0; i < 2; i++) {               // B: 128 rows x 4 chunks (int8)
        int g = tid + i * 256;
        int row = g >> 2, c = g & 3;
        const void* src = Bg + (size_t)row * DIN + k0 + c * 16;
        uint32_t dst = base + ASZ + row * BROW + c * 16;
        asm volatile("cp.async.cg.shared.global [%0], [%1], 16;" :: "r"(dst), "l"(src) : "memory");
    }
    asm volatile("cp.async.commit_group;" ::: "memory");
}

__global__ __launch_bounds__(256, 2)
void gemm_kernel(const float* __restrict__ bias, float* __restrict__ out) {
    extern __shared__ char smem[];
    uint32_t sb = smem_u32(smem);
    int tid = threadIdx.x, wid = tid >> 5, lane = tid & 31;
    int wm = wid & 1;        // 2 warps along M (64 rows each)
    int wn = wid >> 1;       // 4 warps along N (32 cols each)

    // tile map: bm fastest so a wave shares B column strips in L2
    int bm = blockIdx.x & 63;
    int bn = blockIdx.x >> 6;
    int m0 = bm * BM, n0 = bn * BN;

    const __half*  Ag = g_xn + (size_t)m0 * DIN;
    const int8_t*  Bg = g_ws + (size_t)n0 * DIN;

    // A ldmatrix lane address components (fp16, swizzled 128B rows)
    int arow = wm * 64 + (lane & 15);           // + mt*16
    int ahalf = lane >> 4;                      // k half 0/1
    int axm = arow & 7;
    uint32_t aoff = (uint32_t)arow * 128;

    // B ldmatrix lane address: matrix m = lane>>3 covers n-octet, row j = lane&7
    uint32_t boff = (uint32_t)((wn * 32 + ((lane >> 3) << 3) + (lane & 7)) * BROW);

    float acc[4][4][4];
#pragma unroll
    for (int i = 0; i < 4; i++)
#pragma unroll
        for (int j = 0; j < 4; j++)
#pragma unroll
            for (int t = 0; t < 4; t++) acc[i][j][t] = 0.f;

    load_stage(sb, 0, 0, Ag, Bg, tid);
    load_stage(sb, 1, 1, Ag, Bg, tid);

    for (int kc = 0; kc < NK; kc++) {
        if (kc == NK - 1) asm volatile("cp.async.wait_group 0;" ::: "memory");
        else              asm volatile("cp.async.wait_group 1;" ::: "memory");
        __syncthreads();

        int buf = kc % NSTAGE;
        if (kc + 2 < NK) load_stage(sb, (kc + 2) % NSTAGE, kc + 2, Ag, Bg, tid);

        uint32_t abase = sb + buf * STG + aoff;
        uint32_t bbase = sb + buf * STG + ASZ + boff;

#pragma unroll
        for (int kk = 0; kk < 4; kk++) {
            uint32_t afr[4][4];
#pragma unroll
            for (int mt = 0; mt < 4; mt++) {
                int ch = kk * 2 + ahalf;
                ldmx4(afr[mt], abase + mt * 2048 + ((ch ^ axm) << 4));
            }
            // one ldmatrix.x4 over int8-paired data: reg m = B fragment regs
            // for n-tile m after sign-extend expansion
            uint32_t br[4];
            ldmx4(br, bbase + kk * 16);
            uint32_t bfr[4][2];
#pragma unroll
            for (int nt = 0; nt < 4; nt++) {
                uint32_t lo = __byte_perm(br[nt], 0, 0x9180);   // sext bytes 0,1
                uint32_t hi = __byte_perm(br[nt], 0, 0xB3A2);   // sext bytes 2,3
                bfr[nt][0] = sext_to_half2(lo);
                bfr[nt][1] = sext_to_half2(hi);
            }
#pragma unroll
            for (int mt = 0; mt < 4; mt++)
#pragma unroll
                for (int nt = 0; nt < 4; nt++)
                    mma16816(acc[mt][nt], afr[mt], bfr[nt]);
        }
    }

    // epilogue: bias add + store
#pragma unroll
    for (int mt = 0; mt < 4; mt++) {
#pragma unroll
        for (int nt = 0; nt < 4; nt++) {
            int row = m0 + wm * 64 + mt * 16 + (lane >> 2);
            int col = n0 + wn * 32 + nt * 8 + 2 * (lane & 3);
            float2 bv = *(const float2*)(bias + col);
            float2 v0 = { acc[mt][nt][0] + bv.x, acc[mt][nt][1] + bv.y };
            float2 v1 = { acc[mt][nt][2] + bv.x, acc[mt][nt][3] + bv.y };
            *(float2*)(out + (size_t)row * DOUT + col)       = v0;
            *(float2*)(out + (size_t)(row + 8) * DOUT + col) = v1;
        }
    }
}

// ---------------------------------------------------------------------------
// kernel_launch
// ---------------------------------------------------------------------------
extern "C" void kernel_launch(void* const* d_in, const int* in_sizes, int n_in,
                              void* d_out, int out_size) {
    const float* x    = (const float*)d_in[0];
    const float* w    = (const float*)d_in[1];
    const float* bias = (const float*)d_in[2];
    float* out = (float*)d_out;

    cudaFuncSetAttribute(gemm_kernel, cudaFuncAttributeMaxDynamicSharedMemorySize, SMEM_TOTAL);

    ln_kernel<<<TOKENS, 256>>>(x);
    sign_kernel<<<(int)(((size_t)DOUT * DIN / 16) / 256), 256>>>(w);

    int ntiles = (TOKENS / BM) * (DOUT / BN);   // 64 * 128 = 8192
    gemm_kernel<<<ntiles, 256, SMEM_TOTAL>>>(bias, out);
}

// round 7
// speedup vs baseline: 1.1538x; 1.1538x over previous
#include <cuda_runtime.h>
#include <cuda_fp16.h>
#include <cstdint>

#define TOKENS 8192
#define DIN    4096
#define DOUT   16384

// Scratch (device globals are the sanctioned scratch mechanism)
__device__ __half g_xn[(size_t)TOKENS * DIN];   // layernormed x, fp16 (64 MB)
__device__ __half g_ws[(size_t)DOUT * DIN];     // sign(W), fp16 (128 MB)

__device__ __forceinline__ uint32_t smem_u32(const void* p) {
    uint32_t a;
    asm("{ .reg .u64 t; cvta.to.shared.u64 t, %1; cvt.u32.u64 %0, t; }"
        : "=r"(a) : "l"(p));
    return a;
}

// ---------------------------------------------------------------------------
// Kernel 1: row layernorm (fp32 stats, ddof=1), write fp16 to g_xn
// ---------------------------------------------------------------------------
__global__ __launch_bounds__(256) void ln_kernel(const float* __restrict__ x) {
    int row = blockIdx.x;
    const float4* xr = (const float4*)(x + (size_t)row * DIN);
    float4 v[4];
    float s = 0.f, ss = 0.f;
#pragma unroll
    for (int i = 0; i < 4; i++) {
        v[i] = xr[threadIdx.x + i * 256];
        s  += v[i].x + v[i].y + v[i].z + v[i].w;
        ss += v[i].x * v[i].x + v[i].y * v[i].y + v[i].z * v[i].z + v[i].w * v[i].w;
    }
#pragma unroll
    for (int o = 16; o > 0; o >>= 1) {
        s  += __shfl_xor_sync(0xFFFFFFFFu, s, o);
        ss += __shfl_xor_sync(0xFFFFFFFFu, ss, o);
    }
    __shared__ float sh[2][8];
    __shared__ float sh_mean, sh_inv;
    int wid = threadIdx.x >> 5, lane = threadIdx.x & 31;
    if (lane == 0) { sh[0][wid] = s; sh[1][wid] = ss; }
    __syncthreads();
    if (threadIdx.x == 0) {
        float S = 0.f, SS = 0.f;
#pragma unroll
        for (int i = 0; i < 8; i++) { S += sh[0][i]; SS += sh[1][i]; }
        float mean = S * (1.f / DIN);
        float var  = fmaxf((SS - S * mean) * (1.f / (DIN - 1)), 0.f);
        sh_mean = mean;
        sh_inv  = 1.f / (sqrtf(var) + 1e-5f);
    }
    __syncthreads();
    float mean = sh_mean, inv = sh_inv;
    __half2* orow = (__half2*)(g_xn + (size_t)row * DIN);
#pragma unroll
    for (int i = 0; i < 4; i++) {
        int j = threadIdx.x + i * 256;
        orow[j * 2 + 0] = __floats2half2_rn((v[i].x - mean) * inv, (v[i].y - mean) * inv);
        orow[j * 2 + 1] = __floats2half2_rn((v[i].z - mean) * inv, (v[i].w - mean) * inv);
    }
}

// ---------------------------------------------------------------------------
// Kernel 2: binarize weights to fp16 {-1,0,+1}
// ---------------------------------------------------------------------------
__device__ __forceinline__ float sgnf(float a) {
    return (a > 0.f) ? 1.f : ((a < 0.f) ? -1.f : 0.f);
}

__global__ __launch_bounds__(256) void sign_kernel(const float4* __restrict__ w) {
    size_t i = (size_t)blockIdx.x * 256 + threadIdx.x;
    float4 v = w[i];
    __half2* o = (__half2*)g_ws;
    o[2 * i + 0] = __floats2half2_rn(sgnf(v.x), sgnf(v.y));
    o[2 * i + 1] = __floats2half2_rn(sgnf(v.z), sgnf(v.w));
}

// ---------------------------------------------------------------------------
// Kernel 3: HMMA GEMM. CTA = 128 threads (4 warps, 2x2), tile 128x128x64,
//   warp tile 64x64 (min crossbar traffic/FLOP), 3-stage cp.async,
//   2 CTAs/SM (reg cap 256/thread -> 128 accums fit without spill).
// ---------------------------------------------------------------------------
constexpr int BM = 128, BN = 128, BK = 64;
constexpr int NK = DIN / BK;                 // 64 K-chunks
constexpr int ASZ = BM * BK * 2;             // 16 KB
constexpr int BSZ = BN * BK * 2;             // 16 KB
constexpr int STG = ASZ + BSZ;               // 32 KB per stage
constexpr int NSTAGE = 3;
constexpr int SMEM_TOTAL = NSTAGE * STG;     // 96 KB (x2 CTAs = 192 KB/SM)
constexpr int CTA_THREADS = 128;

__device__ __forceinline__ void ldmx4(uint32_t* r, uint32_t addr) {
    asm volatile("ldmatrix.sync.aligned.m8n8.x4.shared.b16 {%0,%1,%2,%3}, [%4];"
                 : "=r"(r[0]), "=r"(r[1]), "=r"(r[2]), "=r"(r[3]) : "r"(addr));
}

__device__ __forceinline__ void mma16816(float* c, const uint32_t* a, const uint32_t* b) {
    asm volatile(
        "mma.sync.aligned.m16n8k16.row.col.f32.f16.f16.f32 "
        "{%0,%1,%2,%3}, {%4,%5,%6,%7}, {%8,%9}, {%0,%1,%2,%3};"
        : "+f"(c[0]), "+f"(c[1]), "+f"(c[2]), "+f"(c[3])
        : "r"(a[0]), "r"(a[1]), "r"(a[2]), "r"(a[3]), "r"(b[0]), "r"(b[1]));
}

// load one 32KB stage with 128 threads: A rows then B rows; XOR-8 swizzle
__device__ __forceinline__ void load_stage(uint32_t sb, int buf, int kc,
                                           const __half* Ag, const __half* Bg, int tid) {
    uint32_t base = sb + buf * STG;
    int k0 = kc * BK;
#pragma unroll
    for (int i = 0; i < 8; i++) {               // A: 128 rows x 8 chunks
        int g = tid + i * CTA_THREADS;
        int row = g >> 3, c = g & 7;
        const void* src = Ag + (size_t)row * DIN + k0 + c * 8;
        uint32_t dst = base + row * 128 + ((c ^ (row & 7)) << 4);
        asm volatile("cp.async.cg.shared.global [%0], [%1], 16;" :: "r"(dst), "l"(src) : "memory");
    }
#pragma unroll
    for (int i = 0; i < 8; i++) {               // B: 128 rows x 8 chunks
        int g = tid + i * CTA_THREADS;
        int row = g >> 3, c = g & 7;
        const void* src = Bg + (size_t)row * DIN + k0 + c * 8;
        uint32_t dst = base + ASZ + row * 128 + ((c ^ (row & 7)) << 4);
        asm volatile("cp.async.cg.shared.global [%0], [%1], 16;" :: "r"(dst), "l"(src) : "memory");
    }
    asm volatile("cp.async.commit_group;" ::: "memory");
}

__global__ __launch_bounds__(CTA_THREADS, 2)
void gemm_kernel(const float* __restrict__ bias, float* __restrict__ out) {
    extern __shared__ char smem[];
    uint32_t sb = smem_u32(smem);
    int tid = threadIdx.x, wid = tid >> 5, lane = tid & 31;
    int wm = wid & 1;        // 2 warps along M (64 rows each)
    int wn = wid >> 1;       // 2 warps along N (64 cols each)

    // tile map: bm fastest so a wave shares B column strips in L2
    int bm = blockIdx.x & 63;
    int bn = blockIdx.x >> 6;
    int m0 = bm * BM, n0 = bn * BN;

    const __half* Ag = g_xn + (size_t)m0 * DIN;
    const __half* Bg = g_ws + (size_t)n0 * DIN;

    // A ldmatrix lane address components
    int arow = wm * 64 + (lane & 15);           // + mt*16
    int ahalf = lane >> 4;                      // k half 0/1
    int axm = arow & 7;
    uint32_t aoff = (uint32_t)arow * 128;
    // B ldmatrix lane address components
    int bg = lane >> 3, bj = lane & 7;
    int brow = wn * 64 + ((bg >> 1) << 3) + bj; // + np*16
    int bhalf = bg & 1;
    int bxm = brow & 7;
    uint32_t boff = (uint32_t)brow * 128;

    float acc[4][8][4];
#pragma unroll
    for (int i = 0; i < 4; i++)
#pragma unroll
        for (int j = 0; j < 8; j++)
#pragma unroll
            for (int t = 0; t < 4; t++) acc[i][j][t] = 0.f;

    load_stage(sb, 0, 0, Ag, Bg, tid);
    load_stage(sb, 1, 1, Ag, Bg, tid);

    for (int kc = 0; kc < NK; kc++) {
        if (kc == NK - 1) asm volatile("cp.async.wait_group 0;" ::: "memory");
        else              asm volatile("cp.async.wait_group 1;" ::: "memory");
        __syncthreads();

        int buf = kc % NSTAGE;
        if (kc + 2 < NK) load_stage(sb, (kc + 2) % NSTAGE, kc + 2, Ag, Bg, tid);

        uint32_t abase = sb + buf * STG + aoff;
        uint32_t bbase = sb + buf * STG + ASZ + boff;

#pragma unroll
        for (int kk = 0; kk < 4; kk++) {
            uint32_t afr[4][4], bfr[4][4];
#pragma unroll
            for (int mt = 0; mt < 4; mt++) {
                int ch = kk * 2 + ahalf;
                ldmx4(afr[mt], abase + mt * 2048 + ((ch ^ axm) << 4));
            }
#pragma unroll
            for (int np = 0; np < 4; np++) {
                int ch = kk * 2 + bhalf;
                ldmx4(bfr[np], bbase + np * 2048 + ((ch ^ bxm) << 4));
            }
#pragma unroll
            for (int mt = 0; mt < 4; mt++)
#pragma unroll
                for (int nt = 0; nt < 8; nt++)
                    mma16816(acc[mt][nt], afr[mt], &bfr[nt >> 1][(nt & 1) * 2]);
        }
    }

    // epilogue: bias add + store
#pragma unroll
    for (int mt = 0; mt < 4; mt++) {
#pragma unroll
        for (int nt = 0; nt < 8; nt++) {
            int row = m0 + wm * 64 + mt * 16 + (lane >> 2);
            int col = n0 + wn * 64 + nt * 8 + 2 * (lane & 3);
            float2 bv = *(const float2*)(bias + col);
            float2 v0 = { acc[mt][nt][0] + bv.x, acc[mt][nt][1] + bv.y };
            float2 v1 = { acc[mt][nt][2] + bv.x, acc[mt][nt][3] + bv.y };
            *(float2*)(out + (size_t)row * DOUT + col)       = v0;
            *(float2*)(out + (size_t)(row + 8) * DOUT + col) = v1;
        }
    }
}

// ---------------------------------------------------------------------------
// kernel_launch
// ---------------------------------------------------------------------------
extern "C" void kernel_launch(void* const* d_in, const int* in_sizes, int n_in,
                              void* d_out, int out_size) {
    const float* x    = (const float*)d_in[0];
    const float* w    = (const float*)d_in[1];
    const float* bias = (const float*)d_in[2];
    float* out = (float*)d_out;

    cudaFuncSetAttribute(gemm_kernel, cudaFuncAttributeMaxDynamicSharedMemorySize, SMEM_TOTAL);

    ln_kernel<<<TOKENS, 256>>>(x);
    sign_kernel<<<(int)(((size_t)DOUT * DIN / 4) / 256), 256>>>((const float4*)w);

    int ntiles = (TOKENS / BM) * (DOUT / BN);   // 64 * 128 = 8192
    gemm_kernel<<<ntiles, CTA_THREADS, SMEM_TOTAL>>>(bias, out);
}

// round 8
// speedup vs baseline: 1.2180x; 1.0556x over previous
#include <cuda_runtime.h>
#include <cuda_fp16.h>
#include <cstdint>

#define TOKENS 8192
#define DIN    4096
#define DOUT   16384

// Scratch (device globals are the sanctioned scratch mechanism)
__device__ __half g_xn[(size_t)TOKENS * DIN];   // layernormed x, fp16 (64 MB)
__device__ __half g_ws[(size_t)DOUT * DIN];     // sign(W), fp16 (128 MB)

__device__ __forceinline__ uint32_t smem_u32(const void* p) {
    uint32_t a;
    asm("{ .reg .u64 t; cvta.to.shared.u64 t, %1; cvt.u32.u64 %0, t; }"
        : "=r"(a) : "l"(p));
    return a;
}

// ---------------------------------------------------------------------------
// Kernel 1: row layernorm (fp32 stats, ddof=1), write fp16 to g_xn
// ---------------------------------------------------------------------------
__global__ __launch_bounds__(256) void ln_kernel(const float* __restrict__ x) {
    int row = blockIdx.x;
    const float4* xr = (const float4*)(x + (size_t)row * DIN);
    float4 v[4];
    float s = 0.f, ss = 0.f;
#pragma unroll
    for (int i = 0; i < 4; i++) {
        v[i] = xr[threadIdx.x + i * 256];
        s  += v[i].x + v[i].y + v[i].z + v[i].w;
        ss += v[i].x * v[i].x + v[i].y * v[i].y + v[i].z * v[i].z + v[i].w * v[i].w;
    }
#pragma unroll
    for (int o = 16; o > 0; o >>= 1) {
        s  += __shfl_xor_sync(0xFFFFFFFFu, s, o);
        ss += __shfl_xor_sync(0xFFFFFFFFu, ss, o);
    }
    __shared__ float sh[2][8];
    __shared__ float sh_mean, sh_inv;
    int wid = threadIdx.x >> 5, lane = threadIdx.x & 31;
    if (lane == 0) { sh[0][wid] = s; sh[1][wid] = ss; }
    __syncthreads();
    if (threadIdx.x == 0) {
        float S = 0.f, SS = 0.f;
#pragma unroll
        for (int i = 0; i < 8; i++) { S += sh[0][i]; SS += sh[1][i]; }
        float mean = S * (1.f / DIN);
        float var  = fmaxf((SS - S * mean) * (1.f / (DIN - 1)), 0.f);
        sh_mean = mean;
        sh_inv  = 1.f / (sqrtf(var) + 1e-5f);
    }
    __syncthreads();
    float mean = sh_mean, inv = sh_inv;
    __half2* orow = (__half2*)(g_xn + (size_t)row * DIN);
#pragma unroll
    for (int i = 0; i < 4; i++) {
        int j = threadIdx.x + i * 256;
        orow[j * 2 + 0] = __floats2half2_rn((v[i].x - mean) * inv, (v[i].y - mean) * inv);
        orow[j * 2 + 1] = __floats2half2_rn((v[i].z - mean) * inv, (v[i].w - mean) * inv);
    }
}

// ---------------------------------------------------------------------------
// Kernel 2: binarize weights to fp16 {-1,0,+1}
// ---------------------------------------------------------------------------
__device__ __forceinline__ float sgnf(float a) {
    return (a > 0.f) ? 1.f : ((a < 0.f) ? -1.f : 0.f);
}

__global__ __launch_bounds__(256) void sign_kernel(const float4* __restrict__ w) {
    size_t i = (size_t)blockIdx.x * 256 + threadIdx.x;
    float4 v = w[i];
    __half2* o = (__half2*)g_ws;
    o[2 * i + 0] = __floats2half2_rn(sgnf(v.x), sgnf(v.y));
    o[2 * i + 1] = __floats2half2_rn(sgnf(v.z), sgnf(v.w));
}

// ---------------------------------------------------------------------------
// Kernel 3: HMMA GEMM. CTA = 128 threads (4 warps, 2x2), tile 128x128x64,
//   warp tile 64x64, 3-stage cp.async, 2 CTAs/SM. cp.async issue burst is
//   placed between kk=0 fragment LDSMs and kk=0 MMAs so the tensor pipe
//   stays fed across the kc boundary.
// ---------------------------------------------------------------------------
constexpr int BM = 128, BN = 128, BK = 64;
constexpr int NK = DIN / BK;                 // 64 K-chunks
constexpr int ASZ = BM * BK * 2;             // 16 KB
constexpr int BSZ = BN * BK * 2;             // 16 KB
constexpr int STG = ASZ + BSZ;               // 32 KB per stage
constexpr int NSTAGE = 3;
constexpr int SMEM_TOTAL = NSTAGE * STG;     // 96 KB (x2 CTAs = 192 KB/SM)
constexpr int CTA_THREADS = 128;

__device__ __forceinline__ void ldmx4(uint32_t* r, uint32_t addr) {
    asm volatile("ldmatrix.sync.aligned.m8n8.x4.shared.b16 {%0,%1,%2,%3}, [%4];"
                 : "=r"(r[0]), "=r"(r[1]), "=r"(r[2]), "=r"(r[3]) : "r"(addr));
}

__device__ __forceinline__ void mma16816(float* c, const uint32_t* a, const uint32_t* b) {
    asm volatile(
        "mma.sync.aligned.m16n8k16.row.col.f32.f16.f16.f32 "
        "{%0,%1,%2,%3}, {%4,%5,%6,%7}, {%8,%9}, {%0,%1,%2,%3};"
        : "+f"(c[0]), "+f"(c[1]), "+f"(c[2]), "+f"(c[3])
        : "r"(a[0]), "r"(a[1]), "r"(a[2]), "r"(a[3]), "r"(b[0]), "r"(b[1]));
}

// issue one 32KB stage with 128 threads: A rows then B rows; XOR-8 swizzle
__device__ __forceinline__ void load_stage(uint32_t sb, int buf, int kc,
                                           const __half* Ag, const __half* Bg, int tid) {
    uint32_t base = sb + buf * STG;
    int k0 = kc * BK;
#pragma unroll
    for (int i = 0; i < 8; i++) {               // A: 128 rows x 8 chunks
        int g = tid + i * CTA_THREADS;
        int row = g >> 3, c = g & 7;
        const void* src = Ag + (size_t)row * DIN + k0 + c * 8;
        uint32_t dst = base + row * 128 + ((c ^ (row & 7)) << 4);
        asm volatile("cp.async.cg.shared.global [%0], [%1], 16;" :: "r"(dst), "l"(src) : "memory");
    }
#pragma unroll
    for (int i = 0; i < 8; i++) {               // B: 128 rows x 8 chunks
        int g = tid + i * CTA_THREADS;
        int row = g >> 3, c = g & 7;
        const void* src = Bg + (size_t)row * DIN + k0 + c * 8;
        uint32_t dst = base + ASZ + row * 128 + ((c ^ (row & 7)) << 4);
        asm volatile("cp.async.cg.shared.global [%0], [%1], 16;" :: "r"(dst), "l"(src) : "memory");
    }
    asm volatile("cp.async.commit_group;" ::: "memory");
}

__global__ __launch_bounds__(CTA_THREADS, 2)
void gemm_kernel(const float* __restrict__ bias, float* __restrict__ out) {
    extern __shared__ char smem[];
    uint32_t sb = smem_u32(smem);
    int tid = threadIdx.x, wid = tid >> 5, lane = tid & 31;
    int wm = wid & 1;        // 2 warps along M (64 rows each)
    int wn = wid >> 1;       // 2 warps along N (64 cols each)

    // tile map: bm fastest so a wave shares B column strips in L2
    int bm = blockIdx.x & 63;
    int bn = blockIdx.x >> 6;
    int m0 = bm * BM, n0 = bn * BN;

    const __half* Ag = g_xn + (size_t)m0 * DIN;
    const __half* Bg = g_ws + (size_t)n0 * DIN;

    // A ldmatrix lane address components
    int arow = wm * 64 + (lane & 15);           // + mt*16
    int ahalf = lane >> 4;                      // k half 0/1
    int axm = arow & 7;
    uint32_t aoff = (uint32_t)arow * 128;
    // B ldmatrix lane address components
    int bg = lane >> 3, bj = lane & 7;
    int brow = wn * 64 + ((bg >> 1) << 3) + bj; // + np*16
    int bhalf = bg & 1;
    int bxm = brow & 7;
    uint32_t boff = (uint32_t)brow * 128;

    float acc[4][8][4];
#pragma unroll
    for (int i = 0; i < 4; i++)
#pragma unroll
        for (int j = 0; j < 8; j++)
#pragma unroll
            for (int t = 0; t < 4; t++) acc[i][j][t] = 0.f;

    load_stage(sb, 0, 0, Ag, Bg, tid);
    load_stage(sb, 1, 1, Ag, Bg, tid);

    for (int kc = 0; kc < NK; kc++) {
        if (kc == NK - 1) asm volatile("cp.async.wait_group 0;" ::: "memory");
        else              asm volatile("cp.async.wait_group 1;" ::: "memory");
        __syncthreads();

        int buf = kc % NSTAGE;
        uint32_t abase = sb + buf * STG + aoff;
        uint32_t bbase = sb + buf * STG + ASZ + boff;

        // kk=0 fragment loads FIRST...
        uint32_t afr[4][4], bfr[4][4];
#pragma unroll
        for (int mt = 0; mt < 4; mt++)
            ldmx4(afr[mt], abase + mt * 2048 + ((ahalf ^ axm) << 4));
#pragma unroll
        for (int np = 0; np < 4; np++)
            ldmx4(bfr[np], bbase + np * 2048 + ((bhalf ^ bxm) << 4));

        // ...then the cp.async issue burst (overlaps LDSM latency + kk=0 MMAs)
        if (kc + 2 < NK) load_stage(sb, (kc + 2) % NSTAGE, kc + 2, Ag, Bg, tid);

        // kk=0 MMAs
#pragma unroll
        for (int mt = 0; mt < 4; mt++)
#pragma unroll
            for (int nt = 0; nt < 8; nt++)
                mma16816(acc[mt][nt], afr[mt], &bfr[nt >> 1][(nt & 1) * 2]);

        // kk = 1..3
#pragma unroll
        for (int kk = 1; kk < 4; kk++) {
#pragma unroll
            for (int mt = 0; mt < 4; mt++) {
                int ch = kk * 2 + ahalf;
                ldmx4(afr[mt], abase + mt * 2048 + ((ch ^ axm) << 4));
            }
#pragma unroll
            for (int np = 0; np < 4; np++) {
                int ch = kk * 2 + bhalf;
                ldmx4(bfr[np], bbase + np * 2048 + ((ch ^ bxm) << 4));
            }
#pragma unroll
            for (int mt = 0; mt < 4; mt++)
#pragma unroll
                for (int nt = 0; nt < 8; nt++)
                    mma16816(acc[mt][nt], afr[mt], &bfr[nt >> 1][(nt & 1) * 2]);
        }
    }

    // epilogue: bias add + store
#pragma unroll
    for (int mt = 0; mt < 4; mt++) {
#pragma unroll
        for (int nt = 0; nt < 8; nt++) {
            int row = m0 + wm * 64 + mt * 16 + (lane >> 2);
            int col = n0 + wn * 64 + nt * 8 + 2 * (lane & 3);
            float2 bv = *(const float2*)(bias + col);
            float2 v0 = { acc[mt][nt][0] + bv.x, acc[mt][nt][1] + bv.y };
            float2 v1 = { acc[mt][nt][2] + bv.x, acc[mt][nt][3] + bv.y };
            *(float2*)(out + (size_t)row * DOUT + col)       = v0;
            *(float2*)(out + (size_t)(row + 8) * DOUT + col) = v1;
        }
    }
}

// ---------------------------------------------------------------------------
// kernel_launch
// ---------------------------------------------------------------------------
extern "C" void kernel_launch(void* const* d_in, const int* in_sizes, int n_in,
                              void* d_out, int out_size) {
    const float* x    = (const float*)d_in[0];
    const float* w    = (const float*)d_in[1];
    const float* bias = (const float*)d_in[2];
    float* out = (float*)d_out;

    cudaFuncSetAttribute(gemm_kernel, cudaFuncAttributeMaxDynamicSharedMemorySize, SMEM_TOTAL);

    ln_kernel<<<TOKENS, 256>>>(x);
    sign_kernel<<<(int)(((size_t)DOUT * DIN / 4) / 256), 256>>>((const float4*)w);

    int ntiles = (TOKENS / BM) * (DOUT / BN);   // 64 * 128 = 8192
    gemm_kernel<<<ntiles, CTA_THREADS, SMEM_TOTAL>>>(bias, out);
}

// round 9
// speedup vs baseline: 1.2317x; 1.0113x over previous
#include <cuda_runtime.h>
#include <cuda_fp16.h>
#include <cstdint>

#define TOKENS 8192
#define DIN    4096
#define DOUT   16384

// Scratch (device globals are the sanctioned scratch mechanism)
__device__ __half g_xn[(size_t)TOKENS * DIN];   // layernormed x, fp16 (64 MB)
__device__ __half g_ws[(size_t)DOUT * DIN];     // sign(W), fp16 (128 MB)

__device__ __forceinline__ uint32_t smem_u32(const void* p) {
    uint32_t a;
    asm("{ .reg .u64 t; cvta.to.shared.u64 t, %1; cvt.u32.u64 %0, t; }"
        : "=r"(a) : "l"(p));
    return a;
}

__device__ __forceinline__ float sgnf(float a) {
    return (a > 0.f) ? 1.f : ((a < 0.f) ? -1.f : 0.f);
}

// ---------------------------------------------------------------------------
// Kernel 1 (fused prep): per-block layernorm row, then grid-stride sign(W)
// ---------------------------------------------------------------------------
__global__ __launch_bounds__(256) void prep_kernel(const float* __restrict__ x,
                                                   const float4* __restrict__ w) {
    // ---- layernorm: one row per block ----
    int row = blockIdx.x;
    {
        const float4* xr = (const float4*)(x + (size_t)row * DIN);
        float4 v[4];
        float s = 0.f, ss = 0.f;
#pragma unroll
        for (int i = 0; i < 4; i++) {
            v[i] = xr[threadIdx.x + i * 256];
            s  += v[i].x + v[i].y + v[i].z + v[i].w;
            ss += v[i].x * v[i].x + v[i].y * v[i].y + v[i].z * v[i].z + v[i].w * v[i].w;
        }
#pragma unroll
        for (int o = 16; o > 0; o >>= 1) {
            s  += __shfl_xor_sync(0xFFFFFFFFu, s, o);
            ss += __shfl_xor_sync(0xFFFFFFFFu, ss, o);
        }
        __shared__ float sh[18];
        int wid = threadIdx.x >> 5, lane = threadIdx.x & 31;
        if (lane == 0) { sh[wid] = s; sh[8 + wid] = ss; }
        __syncthreads();
        if (threadIdx.x == 0) {
            float S = 0.f, SS = 0.f;
#pragma unroll
            for (int i = 0; i < 8; i++) { S += sh[i]; SS += sh[8 + i]; }
            float mean = S * (1.f / DIN);
            float var  = fmaxf((SS - S * mean) * (1.f / (DIN - 1)), 0.f);
            sh[16] = mean;
            sh[17] = 1.f / (sqrtf(var) + 1e-5f);
        }
        __syncthreads();
        float mean = sh[16], inv = sh[17];
        __half2* orow = (__half2*)(g_xn + (size_t)row * DIN);
#pragma unroll
        for (int i = 0; i < 4; i++) {
            int j = threadIdx.x + i * 256;
            orow[j * 2 + 0] = __floats2half2_rn((v[i].x - mean) * inv, (v[i].y - mean) * inv);
            orow[j * 2 + 1] = __floats2half2_rn((v[i].z - mean) * inv, (v[i].w - mean) * inv);
        }
    }

    // ---- sign(W): grid-stride over 16M float4 groups ----
    {
        size_t total = (size_t)DOUT * DIN / 4;
        size_t stride = (size_t)gridDim.x * 256;
        __half2* o = (__half2*)g_ws;
        for (size_t i = (size_t)blockIdx.x * 256 + threadIdx.x; i < total; i += stride) {
            float4 v = w[i];
            o[2 * i + 0] = __floats2half2_rn(sgnf(v.x), sgnf(v.y));
            o[2 * i + 1] = __floats2half2_rn(sgnf(v.z), sgnf(v.w));
        }
    }
}

// ---------------------------------------------------------------------------
// Kernel 2: HMMA GEMM. CTA = 128 threads (4 warps, 2x2), tile 128x128x64,
//   warp tile 64x64, 3-stage cp.async, 2 CTAs/SM. cp.async bursts split and
//   interleaved with fragment LDSMs; epilogue uses streaming stores (.cs)
//   so the output never evicts wave-resident A from L2.
// ---------------------------------------------------------------------------
constexpr int BM = 128, BN = 128, BK = 64;
constexpr int NK = DIN / BK;                 // 64 K-chunks
constexpr int ASZ = BM * BK * 2;             // 16 KB
constexpr int BSZ = BN * BK * 2;             // 16 KB
constexpr int STG = ASZ + BSZ;               // 32 KB per stage
constexpr int NSTAGE = 3;
constexpr int SMEM_TOTAL = NSTAGE * STG;     // 96 KB (x2 CTAs = 192 KB/SM)
constexpr int CTA_THREADS = 128;

__device__ __forceinline__ void ldmx4(uint32_t* r, uint32_t addr) {
    asm volatile("ldmatrix.sync.aligned.m8n8.x4.shared.b16 {%0,%1,%2,%3}, [%4];"
                 : "=r"(r[0]), "=r"(r[1]), "=r"(r[2]), "=r"(r[3]) : "r"(addr));
}

__device__ __forceinline__ void mma16816(float* c, const uint32_t* a, const uint32_t* b) {
    asm volatile(
        "mma.sync.aligned.m16n8k16.row.col.f32.f16.f16.f32 "
        "{%0,%1,%2,%3}, {%4,%5,%6,%7}, {%8,%9}, {%0,%1,%2,%3};"
        : "+f"(c[0]), "+f"(c[1]), "+f"(c[2]), "+f"(c[3])
        : "r"(a[0]), "r"(a[1]), "r"(a[2]), "r"(a[3]), "r"(b[0]), "r"(b[1]));
}

// A-half of a stage (8 cp.async per thread over 128 threads)
__device__ __forceinline__ void load_stage_A(uint32_t sb, int buf, int kc,
                                             const __half* Ag, int tid) {
    uint32_t base = sb + buf * STG;
    int k0 = kc * BK;
#pragma unroll
    for (int i = 0; i < 8; i++) {
        int g = tid + i * CTA_THREADS;
        int row = g >> 3, c = g & 7;
        const void* src = Ag + (size_t)row * DIN + k0 + c * 8;
        uint32_t dst = base + row * 128 + ((c ^ (row & 7)) << 4);
        asm volatile("cp.async.cg.shared.global [%0], [%1], 16;" :: "r"(dst), "l"(src) : "memory");
    }
}

// B-half of a stage
__device__ __forceinline__ void load_stage_B(uint32_t sb, int buf, int kc,
                                             const __half* Bg, int tid) {
    uint32_t base = sb + buf * STG + ASZ;
    int k0 = kc * BK;
#pragma unroll
    for (int i = 0; i < 8; i++) {
        int g = tid + i * CTA_THREADS;
        int row = g >> 3, c = g & 7;
        const void* src = Bg + (size_t)row * DIN + k0 + c * 8;
        uint32_t dst = base + row * 128 + ((c ^ (row & 7)) << 4);
        asm volatile("cp.async.cg.shared.global [%0], [%1], 16;" :: "r"(dst), "l"(src) : "memory");
    }
}

__global__ __launch_bounds__(CTA_THREADS, 2)
void gemm_kernel(const float* __restrict__ bias, float* __restrict__ out) {
    extern __shared__ char smem[];
    uint32_t sb = smem_u32(smem);
    int tid = threadIdx.x, wid = tid >> 5, lane = tid & 31;
    int wm = wid & 1;        // 2 warps along M (64 rows each)
    int wn = wid >> 1;       // 2 warps along N (64 cols each)

    // tile map: bm fastest so a wave shares B column strips + keeps A L2-resident
    int bm = blockIdx.x & 63;
    int bn = blockIdx.x >> 6;
    int m0 = bm * BM, n0 = bn * BN;

    const __half* Ag = g_xn + (size_t)m0 * DIN;
    const __half* Bg = g_ws + (size_t)n0 * DIN;

    // A ldmatrix lane address components
    int arow = wm * 64 + (lane & 15);           // + mt*16
    int ahalf = lane >> 4;                      // k half 0/1
    int axm = arow & 7;
    uint32_t aoff = (uint32_t)arow * 128;
    // B ldmatrix lane address components
    int bg = lane >> 3, bj = lane & 7;
    int brow = wn * 64 + ((bg >> 1) << 3) + bj; // + np*16
    int bhalf = bg & 1;
    int bxm = brow & 7;
    uint32_t boff = (uint32_t)brow * 128;

    float acc[4][8][4];
#pragma unroll
    for (int i = 0; i < 4; i++)
#pragma unroll
        for (int j = 0; j < 8; j++)
#pragma unroll
            for (int t = 0; t < 4; t++) acc[i][j][t] = 0.f;

    load_stage_A(sb, 0, 0, Ag, tid);
    load_stage_B(sb, 0, 0, Bg, tid);
    asm volatile("cp.async.commit_group;" ::: "memory");
    load_stage_A(sb, 1, 1, Ag, tid);
    load_stage_B(sb, 1, 1, Bg, tid);
    asm volatile("cp.async.commit_group;" ::: "memory");

    for (int kc = 0; kc < NK; kc++) {
        if (kc == NK - 1) asm volatile("cp.async.wait_group 0;" ::: "memory");
        else              asm volatile("cp.async.wait_group 1;" ::: "memory");
        __syncthreads();

        int buf = kc % NSTAGE;
        int pbuf = (kc + 2) % NSTAGE;
        bool pf = (kc + 2 < NK);
        uint32_t abase = sb + buf * STG + aoff;
        uint32_t bbase = sb + buf * STG + ASZ + boff;

        uint32_t afr[4][4], bfr[4][4];

        // kk=0 fragment loads, A-prefetch burst between LDSM and MMA
#pragma unroll
        for (int mt = 0; mt < 4; mt++)
            ldmx4(afr[mt], abase + mt * 2048 + ((ahalf ^ axm) << 4));
#pragma unroll
        for (int np = 0; np < 4; np++)
            ldmx4(bfr[np], bbase + np * 2048 + ((bhalf ^ bxm) << 4));

        if (pf) load_stage_A(sb, pbuf, kc + 2, Ag, tid);

#pragma unroll
        for (int mt = 0; mt < 4; mt++)
#pragma unroll
            for (int nt = 0; nt < 8; nt++)
                mma16816(acc[mt][nt], afr[mt], &bfr[nt >> 1][(nt & 1) * 2]);

        // kk=1 fragment loads, B-prefetch burst between LDSM and MMA
#pragma unroll
        for (int mt = 0; mt < 4; mt++)
            ldmx4(afr[mt], abase + mt * 2048 + (((2 + ahalf) ^ axm) << 4));
#pragma unroll
        for (int np = 0; np < 4; np++)
            ldmx4(bfr[np], bbase + np * 2048 + (((2 + bhalf) ^ bxm) << 4));

        if (pf) load_stage_B(sb, pbuf, kc + 2, Bg, tid);
        asm volatile("cp.async.commit_group;" ::: "memory");

#pragma unroll
        for (int mt = 0; mt < 4; mt++)
#pragma unroll
            for (int nt = 0; nt < 8; nt++)
                mma16816(acc[mt][nt], afr[mt], &bfr[nt >> 1][(nt & 1) * 2]);

        // kk = 2..3
#pragma unroll
        for (int kk = 2; kk < 4; kk++) {
#pragma unroll
            for (int mt = 0; mt < 4; mt++) {
                int ch = kk * 2 + ahalf;
                ldmx4(afr[mt], abase + mt * 2048 + ((ch ^ axm) << 4));
            }
#pragma unroll
            for (int np = 0; np < 4; np++) {
                int ch = kk * 2 + bhalf;
                ldmx4(bfr[np], bbase + np * 2048 + ((ch ^ bxm) << 4));
            }
#pragma unroll
            for (int mt = 0; mt < 4; mt++)
#pragma unroll
                for (int nt = 0; nt < 8; nt++)
                    mma16816(acc[mt][nt], afr[mt], &bfr[nt >> 1][(nt & 1) * 2]);
        }
    }

    // epilogue: bias add + streaming store (evict-first: don't thrash L2)
#pragma unroll
    for (int mt = 0; mt < 4; mt++) {
#pragma unroll
        for (int nt = 0; nt < 8; nt++) {
            int row = m0 + wm * 64 + mt * 16 + (lane >> 2);
            int col = n0 + wn * 64 + nt * 8 + 2 * (lane & 3);
            float2 bv;
            asm volatile("ld.global.nc.v2.f32 {%0,%1}, [%2];"
                         : "=f"(bv.x), "=f"(bv.y) : "l"(bias + col));
            float* p0 = out + (size_t)row * DOUT + col;
            float* p1 = out + (size_t)(row + 8) * DOUT + col;
            asm volatile("st.global.cs.v2.f32 [%0], {%1,%2};"
                         :: "l"(p0), "f"(acc[mt][nt][0] + bv.x), "f"(acc[mt][nt][1] + bv.y)
                         : "memory");
            asm volatile("st.global.cs.v2.f32 [%0], {%1,%2};"
                         :: "l"(p1), "f"(acc[mt][nt][2] + bv.x), "f"(acc[mt][nt][3] + bv.y)
                         : "memory");
        }
    }
}

// ---------------------------------------------------------------------------
// kernel_launch
// ---------------------------------------------------------------------------
extern "C" void kernel_launch(void* const* d_in, const int* in_sizes, int n_in,
                              void* d_out, int out_size) {
    const float* x    = (const float*)d_in[0];
    const float* w    = (const float*)d_in[1];
    const float* bias = (const float*)d_in[2];
    float* out = (float*)d_out;

    cudaFuncSetAttribute(gemm_kernel, cudaFuncAttributeMaxDynamicSharedMemorySize, SMEM_TOTAL);

    prep_kernel<<<TOKENS, 256>>>(x, (const float4*)w);

    int ntiles = (TOKENS / BM) * (DOUT / BN);   // 64 * 128 = 8192
    gemm_kernel<<<ntiles, CTA_THREADS, SMEM_TOTAL>>>(bias, out);
}